// round 14
// baseline (speedup 1.0000x reference)
#include <cuda_runtime.h>
#include <cstdint>

#define B_TOT 16384
#define T_SEQ 784
#define HID   30
#define NCLS  10
#define NJP   16          // 15 h-pairs (cols 0..29) + 1 x-pair
#define RPT   8           // rows per thread (30 padded to 32, 4 subs x 8)
#define SUBS  4
#define WSTRIDE (NJP * RPT + 2)   // 130 u64 per sub: +16B pad => subs hit disjoint banks

// Compiler scheduling fence: forbids ptxas from hoisting SMEM loads across it.
// R4/R13 showed that without this, ptxas prefetches the whole weight stream,
// balloons to 255 regs and spills (L1 80%, ~2900 cyc/step vs ~200 cyc chain).
#define SCHED_FENCE() asm volatile("" ::: "memory")

typedef unsigned long long u64;

// ---- packed f32x2 helpers (Blackwell FFMA2 path, PTX-only) ----
__device__ __forceinline__ u64 pk2(float lo, float hi) {
    u64 r; asm("mov.b64 %0, {%1, %2};" : "=l"(r) : "f"(lo), "f"(hi)); return r;
}
__device__ __forceinline__ void upk2(float& lo, float& hi, u64 v) {
    asm("mov.b64 {%0, %1}, %2;" : "=f"(lo), "=f"(hi) : "l"(v));
}
__device__ __forceinline__ u64 ffma2(u64 a, u64 b, u64 c) {
    u64 d; asm("fma.rn.f32x2 %0, %1, %2, %3;" : "=l"(d) : "l"(a), "l"(b), "l"(c));
    return d;
}
__device__ __forceinline__ u64 fmul2(u64 a, u64 b) {
    u64 d; asm("mul.rn.f32x2 %0, %1, %2;" : "=l"(d) : "l"(a), "l"(b));
    return d;
}

// 4 threads per batch element (sub = tid&3 owns rows 8*sub..8*sub+7; rows
// 30,31 zero-padded). Weight contraction in groups of 4 column-pairs with a
// scheduling fence between groups so the live LDS window stays at 16
// ulonglong2 (32 regs). __launch_bounds__(128, 3) caps regs at 170 (above the
// ~110 appetite, unlike R11's 128 cap) and guarantees 3 CTAs/SM -> all 512
// CTAs resident in one wave (~3.5 warps/SMSP).
__global__ void __launch_bounds__(128, 3)
rnn_modrelu_kernel(const float* __restrict__ inputs,   // [B, 784]
                   const float* __restrict__ W_ih,     // [30, 1]
                   const float* __restrict__ W_hh,     // [30, 30]
                   const float* __restrict__ b_mod,    // [30]
                   const float* __restrict__ W_lin,    // [10, 30]
                   const float* __restrict__ b_lin,    // [10]
                   float* __restrict__ out)            // [B, 10]
{
    // wts[sub*WSTRIDE + jp*8 + k]: row i=8*sub+k, col pair jp
    //   jp<15 : (W_hh[i][2jp], W_hh[i][2jp+1])   (zero if i>=30)
    //   jp=15 : (W_ih[i], 0)
    __shared__ __align__(16) u64 wts[SUBS * WSTRIDE];

    const int tid = threadIdx.x;
    for (int idx = tid; idx < SUBS * NJP * RPT; idx += 128) {
        const int s  = idx / (NJP * RPT);
        const int rm = idx % (NJP * RPT);
        const int jp = rm / RPT;
        const int k  = rm % RPT;
        const int i  = s * RPT + k;
        float lo = 0.0f, hi = 0.0f;
        if (i < HID) {
            if (jp < 15) { lo = W_hh[i * HID + 2 * jp]; hi = W_hh[i * HID + 2 * jp + 1]; }
            else         { lo = W_ih[i]; }
        }
        wts[s * WSTRIDE + jp * RPT + k] = pk2(lo, hi);
    }
    __syncthreads();

    const int lane = tid & 31;
    const int sub  = tid & 3;
    const int elem = blockIdx.x * 32 + (tid >> 2);

    float bmr[RPT];
#pragma unroll
    for (int r = 0; r < RPT; r++) {
        const int i = sub * RPT + r;
        bmr[r] = (i < HID) ? __ldg(&b_mod[i]) : 0.0f;
    }

    const float2* __restrict__ xrow =
        reinterpret_cast<const float2*>(inputs + (size_t)elem * T_SEQ);
    const ulonglong2* __restrict__ wp =
        reinterpret_cast<const ulonglong2*>(wts + sub * WSTRIDE);

    u64 hfull[NJP];
#pragma unroll
    for (int p = 0; p < NJP; p++) hfull[p] = 0ull;
    u64 own[4] = {0ull, 0ull, 0ull, 0ull};

    auto step = [&](float x) {
        hfull[15] = pk2(x, 0.0f);
        u64 acc[RPT];
        // ---- group 0: jp 0..3 (jp 0 initializes accumulators) ----
        {
#pragma unroll
            for (int rp = 0; rp < 4; rp++) {
                ulonglong2 w = wp[rp];
                acc[2 * rp]     = fmul2(w.x, hfull[0]);
                acc[2 * rp + 1] = fmul2(w.y, hfull[0]);
            }
#pragma unroll
            for (int jp = 1; jp < 4; jp++) {
                const u64 hj = hfull[jp];
#pragma unroll
                for (int rp = 0; rp < 4; rp++) {
                    ulonglong2 w = wp[jp * 4 + rp];
                    acc[2 * rp]     = ffma2(w.x, hj, acc[2 * rp]);
                    acc[2 * rp + 1] = ffma2(w.y, hj, acc[2 * rp + 1]);
                }
            }
        }
        SCHED_FENCE();
        // ---- groups 1..3: jp 4..15, fenced every 4 jp ----
#pragma unroll
        for (int g = 1; g < 4; g++) {
#pragma unroll
            for (int jj = 0; jj < 4; jj++) {
                const int jp = g * 4 + jj;
                const u64 hj = hfull[jp];
#pragma unroll
                for (int rp = 0; rp < 4; rp++) {
                    ulonglong2 w = wp[jp * 4 + rp];
                    acc[2 * rp]     = ffma2(w.x, hj, acc[2 * rp]);
                    acc[2 * rp + 1] = ffma2(w.y, hj, acc[2 * rp + 1]);
                }
            }
            SCHED_FENCE();
        }
        // horizontal reduce + modReLU on own 8 rows (pad rows yield exactly 0)
        float hn[RPT];
#pragma unroll
        for (int r = 0; r < RPT; r++) {
            float lo, hi;
            upk2(lo, hi, acc[r]);
            const float z = lo + hi;
            const float m = fmaxf(fabsf(z) + bmr[r], 0.0f);
            hn[r] = copysignf(m, z);
        }
#pragma unroll
        for (int rp = 0; rp < 4; rp++) own[rp] = pk2(hn[2 * rp], hn[2 * rp + 1]);
        // broadcast the 15 live h'-pairs across the quad (pair p owned by sub p>>2)
#pragma unroll
        for (int p = 0; p < 15; p++) {
            const int src = (lane & ~3) | (p >> 2);
            hfull[p] = __shfl_sync(0xffffffffu, own[p & 3], src);
        }
    };

    float2 xv = __ldg(&xrow[0]);
    const int NIT = T_SEQ / 2;  // 392
    for (int t2 = 0; t2 < NIT; ++t2) {
        const unsigned nidx = min((unsigned)(t2 + 1), (unsigned)(NIT - 1));
        float2 xn = __ldg(&xrow[nidx]);
        step(xv.x);
        step(xv.y);
        xv = xn;
    }

    // Linear head: full h is register-resident in every thread; sub s does
    // classes {s, s+4, s+8} (covers 0..9 across the quad).
    float h[HID];
#pragma unroll
    for (int p = 0; p < 15; p++) upk2(h[2 * p], h[2 * p + 1], hfull[p]);

    for (int c = sub; c < NCLS; c += SUBS) {
        float a = __ldg(&b_lin[c]);
#pragma unroll
        for (int i = 0; i < HID; i++)
            a = fmaf(__ldg(&W_lin[c * HID + i]), h[i], a);
        out[(size_t)elem * NCLS + c] = a;
    }
}

extern "C" void kernel_launch(void* const* d_in, const int* in_sizes, int n_in,
                              void* d_out, int out_size) {
    const float* inputs = (const float*)d_in[0];
    const float* W_ih   = (const float*)d_in[1];
    const float* W_hh   = (const float*)d_in[2];
    const float* b_mod  = (const float*)d_in[3];
    const float* W_lin  = (const float*)d_in[4];
    const float* b_lin  = (const float*)d_in[5];
    float* out = (float*)d_out;

    // 4 threads per element: 16384*4 = 65536 threads = 512 CTAs x 128
    rnn_modrelu_kernel<<<B_TOT / 32, 128>>>(inputs, W_ih, W_hh, b_mod,
                                            W_lin, b_lin, out);
}

// round 15
// speedup vs baseline: 2.2617x; 2.2617x over previous
#include <cuda_runtime.h>
#include <cstdint>

#define B_TOT 16384
#define T_SEQ 784
#define HID   30
#define NCLS  10
#define NJP   16     // 15 h-pairs (cols 0..29) + 1 x-pair
#define HSTRIDE 17   // u64 stride of per-thread h slot: 32 lanes cover all banks in 2 phases

typedef unsigned long long u64;

// ---- packed f32x2 helpers (Blackwell FFMA2 path, PTX-only) ----
__device__ __forceinline__ u64 pk2(float lo, float hi) {
    u64 r; asm("mov.b64 %0, {%1, %2};" : "=l"(r) : "f"(lo), "f"(hi)); return r;
}
__device__ __forceinline__ void upk2(float& lo, float& hi, u64 v) {
    asm("mov.b64 {%0, %1}, %2;" : "=f"(lo), "=f"(hi) : "l"(v));
}
__device__ __forceinline__ u64 ffma2(u64 a, u64 b, u64 c) {
    u64 d; asm("fma.rn.f32x2 %0, %1, %2, %3;" : "=l"(d) : "l"(a), "l"(b), "l"(c));
    return d;
}

// One thread = one batch element (best warp-slot efficiency: every lane does
// independent full work). h lives in SMEM, PRIVATE per thread (no sync needed),
// so the contraction runs as a REAL runtime loop over the 16 column-pairs with
// a ~50-instruction body. This structurally bounds ptxas's scheduling window:
// R4/R13 (full unroll, natural alloc) ballooned to 255 regs + spills (1202us);
// R11/R14 (capped 128/170) spilled harder (3048/2690us). Fences didn't help.
// The backward branch is the only thing ptxas cannot hoist loads across.
__global__ void __launch_bounds__(128)
rnn_modrelu_kernel(const float* __restrict__ inputs,   // [B, 784]
                   const float* __restrict__ W_ih,     // [30, 1]
                   const float* __restrict__ W_hh,     // [30, 30]
                   const float* __restrict__ b_mod,    // [30]
                   const float* __restrict__ W_lin,    // [10, 30]
                   const float* __restrict__ b_lin,    // [10]
                   float* __restrict__ out)            // [B, 10]
{
    // w2s[jp][i] = packed (W_hh[i][2jp], W_hh[i][2jp+1]) for jp<15,
    //              (W_ih[i], 0) for jp=15.  Row = 240 B, 16B-aligned.
    __shared__ __align__(16) u64 w2s[NJP][HID];
    // Per-thread h: 16 packed pairs (slot 15 holds the x-pair), stride 17.
    __shared__ __align__(16) u64 hsm[128 * HSTRIDE];

    const int tid = threadIdx.x;
    for (int idx = tid; idx < NJP * HID; idx += 128) {
        const int jp = idx / HID, i = idx % HID;
        float lo, hi;
        if (jp < 15) { lo = W_hh[i * HID + 2 * jp]; hi = W_hh[i * HID + 2 * jp + 1]; }
        else         { lo = W_ih[i];                hi = 0.0f; }
        w2s[jp][i] = pk2(lo, hi);
    }
    __syncthreads();

    u64* __restrict__ hme = &hsm[tid * HSTRIDE];
#pragma unroll
    for (int p = 0; p < 15; p++) hme[p] = 0ull;   // h0 = 0

    float bm[HID];
#pragma unroll
    for (int i = 0; i < HID; i++) bm[i] = __ldg(&b_mod[i]);

    const int b = blockIdx.x * 128 + tid;
    const float2* __restrict__ xrow =
        reinterpret_cast<const float2*>(inputs + (size_t)b * T_SEQ);

    auto step = [&](float x) {
        hme[15] = pk2(x, 0.0f);                   // STS.64 of the x-pair
        u64 acc[HID];
#pragma unroll
        for (int i = 0; i < HID; i++) acc[i] = 0ull;

        // REAL loop: ~50-instr body, window bounded by the backward branch.
#pragma unroll 1
        for (int jp = 0; jp < NJP; jp++) {
            const u64 hj = hme[jp];               // LDS.64 (own slot, 2 wf/warp)
            const ulonglong2* __restrict__ wrow =
                reinterpret_cast<const ulonglong2*>(&w2s[jp][0]);
#pragma unroll
            for (int i2 = 0; i2 < 15; i2++) {
                ulonglong2 w = wrow[i2];          // broadcast LDS.128
                acc[2 * i2]     = ffma2(w.x, hj, acc[2 * i2]);
                acc[2 * i2 + 1] = ffma2(w.y, hj, acc[2 * i2 + 1]);
            }
        }

        // horizontal reduce + modReLU, packed write-back to own SMEM h
#pragma unroll
        for (int p = 0; p < 15; p++) {
            float l0, u0, l1, u1;
            upk2(l0, u0, acc[2 * p]);
            upk2(l1, u1, acc[2 * p + 1]);
            const float z0 = l0 + u0;
            const float z1 = l1 + u1;
            const float m0 = fmaxf(fabsf(z0) + bm[2 * p], 0.0f);
            const float m1 = fmaxf(fabsf(z1) + bm[2 * p + 1], 0.0f);
            hme[p] = pk2(copysignf(m0, z0), copysignf(m1, z1));
        }
    };

    float2 xv = __ldg(&xrow[0]);
    const int NIT = T_SEQ / 2;  // 392
    for (int t2 = 0; t2 < NIT; ++t2) {
        const unsigned nidx = min((unsigned)(t2 + 1), (unsigned)(NIT - 1));
        float2 xn = __ldg(&xrow[nidx]);
        step(xv.x);
        step(xv.y);
        xv = xn;
    }

    // Linear head: read final h back from own SMEM slot.
    float h[HID];
#pragma unroll
    for (int p = 0; p < 15; p++) upk2(h[2 * p], h[2 * p + 1], hme[p]);

#pragma unroll
    for (int c = 0; c < NCLS; c++) {
        float a = __ldg(&b_lin[c]);
#pragma unroll
        for (int i = 0; i < HID; i++)
            a = fmaf(__ldg(&W_lin[c * HID + i]), h[i], a);
        out[(size_t)b * NCLS + c] = a;
    }
}

extern "C" void kernel_launch(void* const* d_in, const int* in_sizes, int n_in,
                              void* d_out, int out_size) {
    const float* inputs = (const float*)d_in[0];
    const float* W_ih   = (const float*)d_in[1];
    const float* W_hh   = (const float*)d_in[2];
    const float* b_mod  = (const float*)d_in[3];
    const float* W_lin  = (const float*)d_in[4];
    const float* b_lin  = (const float*)d_in[5];
    float* out = (float*)d_out;

    rnn_modrelu_kernel<<<B_TOT / 128, 128>>>(inputs, W_ih, W_hh, b_mod,
                                             W_lin, b_lin, out);
}